// round 1
// baseline (speedup 1.0000x reference)
#include <cuda_runtime.h>

typedef unsigned long long u64;
typedef unsigned int u32;

#define IMG_W 2048
#define IMG_H 2048
#define NWORDS 32               // 32 x u64 = 2048 bits per column
#define NPIX (IMG_W * IMG_H)

// Bit grids, column-major: word (c, w) holds rows [64w, 64w+63] of column c.
__device__ u64 d_A[IMG_W * NWORDS];   // active mask (starts as thin >= 3)
__device__ u64 d_L[IMG_W * NWORDS];   // weak mask   (thin >= 1)

// ---------------------------------------------------------------------------
// low/high outputs (elementwise)
// ---------------------------------------------------------------------------
__global__ void k_lowhigh(const float* __restrict__ thin, float* __restrict__ out) {
    int i = blockIdx.x * blockDim.x + threadIdx.x;
    float v = thin[i];
    out[i]        = (v < 1.0f) ? 0.0f : v;   // low
    out[NPIX + i] = (v < 3.0f) ? 0.0f : v;   // high
}

// ---------------------------------------------------------------------------
// Pack L and initial A into bit grids. Thread (c, w) builds one u64 word.
// Loads are coalesced across the 32 columns of a warp.
// ---------------------------------------------------------------------------
__global__ void k_bitpack(const float* __restrict__ thin) {
    int c = blockIdx.x * 32 + threadIdx.x;
    int w = blockIdx.y * blockDim.y + threadIdx.y;
    u64 L = 0, A = 0;
    const float* base = thin + (size_t)(w * 64) * IMG_W + c;
    #pragma unroll 8
    for (int b = 0; b < 64; ++b) {
        float v = base[(size_t)b * IMG_W];
        L |= ((u64)(v >= 1.0f)) << b;
        A |= ((u64)(v >= 3.0f)) << b;
    }
    d_L[c * NWORDS + w] = L;
    d_A[c * NWORDS + w] = A;
}

// ---------------------------------------------------------------------------
// One directional trace pass, executed by a single warp.
// Lane k owns 64 rows (virtual rows 64k..64k+63; for YR passes the virtual
// row order is the reverse of real rows: load = brevll + lane mirror).
//
// Per column cx:
//   g = A & interior, p = L & interior          (g subset of p always)
//   s_i = g_i | (p_i & s_{i-1})   == carry chain of (p + g)  [gated-or scan]
//   cross-lane carries via 2 ballots + scalar 33-bit add trick
//   up/dn neighbor bits recovered from carry mask C + 2 early ballots (no shfl)
//   A[:,cx-1] |= side & L ; A[:,cx] |= mid & L ; A[:,cx+1] |= side & L
// Column cx-1 is final for the pass -> store; cx,cx+1 stay in registers.
// ---------------------------------------------------------------------------
template <bool XR, bool YR>
__device__ __forceinline__ void trace_pass(const int lane) {
    const u32 FULL = 0xffffffffu;
    const int gw = YR ? (NWORDS - 1 - lane) : lane;   // gmem word this lane owns

    u64 INTM = ~0ull;                                  // interior rows mask
    if (lane == 0)          INTM &= ~1ull;             // virtual row 0
    if (lane == NWORDS - 1) INTM &= 0x7fffffffffffffffull; // virtual row 2047

    const int dx = XR ? -1 : 1;
    int cx = XR ? (IMG_W - 2) : 1;

    u64*       Abase = d_A + gw;
    const u64* Lbase = d_L + gw;

    auto ldA = [&](int c) -> u64 { u64 v = Abase[c * NWORDS]; return YR ? __brevll(v) : v; };
    auto ldL = [&](int c) -> u64 { u64 v = Lbase[c * NWORDS]; return YR ? __brevll(v) : v; };
    auto stA = [&](int c, u64 v) { Abase[c * NWORDS] = YR ? __brevll(v) : v; };

    // Rolling window + prefetch depth 3 (loads always see pre-pass data;
    // in-pass updates to these columns travel in the rolling registers).
    u64 Aprev = ldA(cx - dx), Acur = ldA(cx), Anext = ldA(cx + dx);
    u64 An2 = ldA(cx + 2 * dx), An3 = ldA(cx + 3 * dx);
    u64 Lprev = ldL(cx - dx), Lcur = ldL(cx), Lnext = ldL(cx + dx);
    u64 Ln2 = ldL(cx + 2 * dx), Ln3 = ldL(cx + 3 * dx);

    #pragma unroll 1
    for (int i = 0; i < IMG_W - 2; ++i) {
        u64 g = Acur & INTM;
        u64 p = Lcur & INTM;
        u64 sum0 = p + g;
        // lane-level generate / propagate + bit-0 info for the 'up' shift
        u32 G   = __ballot_sync(FULL, sum0 < p);          // carry-out with cin=0
        u32 P   = __ballot_sync(FULL, sum0 == ~0ull);     // propagates cin
        u32 Bg0 = __ballot_sync(FULL, ((u32)g & 1u) != 0u);
        u32 Bp0 = __ballot_sync(FULL, ((u32)p & 1u) != 0u);
        // carry-in per lane: bits of ((P+G)^P^G); bit32 = total carry-out
        u64 C   = ((u64)P + (u64)G) ^ (u64)P ^ (u64)G;
        u64 cin = (C >> lane) & 1ull;
        u64 sum = sum0 + cin;
        u64 cb  = sum ^ p ^ g;                            // carry-in bits in-word
        u64 s   = (cb >> 1) | (((C >> (lane + 1)) & 1ull) << 63);
        // bit0 of each lane's s (for 'up' across lane boundary), scalar:
        u32 S0  = Bg0 | (Bp0 & (u32)C);
        u64 up  = (s >> 1) | ((((u64)S0 >> (lane + 1)) & 1ull) << 63);
        u64 dn  = (s << 1) | cin;                         // bit0 = carry-in = s[-1]
        u64 mid  = up | dn;
        u64 side = mid | s;

        stA(cx - dx, Aprev | (side & Lprev));             // final for this pass
        u64 AcurN = Acur | (mid & Lcur);
        Anext |= side & Lnext;                            // feeds next step (critical)

        // rotate window
        Aprev = AcurN; Acur = Anext; Anext = An2; An2 = An3;
        Lprev = Lcur;  Lcur = Lnext; Lnext = Ln2; Ln2 = Ln3;
        cx += dx;
        int lc = cx + 3 * dx;
        if ((u32)lc < (u32)IMG_W) { An3 = ldA(lc); Ln3 = ldL(lc); }
    }
    // flush the last two columns
    stA(cx - dx, Aprev);
    stA(cx, Acur);
}

__global__ void __launch_bounds__(32, 1) k_trace() {
    const int lane = threadIdx.x;
    trace_pass<false, false>(lane);
    __threadfence_block(); __syncwarp();
    trace_pass<true, true>(lane);
    __threadfence_block(); __syncwarp();
    trace_pass<false, true>(lane);
    __threadfence_block(); __syncwarp();
    trace_pass<true, false>(lane);
}

// ---------------------------------------------------------------------------
// final = A ? thin : 0   (A superset of strong pixels, values are exact copies)
// ---------------------------------------------------------------------------
__global__ void k_final(const float* __restrict__ thin, float* __restrict__ out) {
    int i = blockIdx.x * blockDim.x + threadIdx.x;
    int r = i >> 11;          // row
    int c = i & (IMG_W - 1);  // col
    u64 w = d_A[c * NWORDS + (r >> 6)];
    bool act = (w >> (r & 63)) & 1ull;
    out[2 * NPIX + i] = act ? thin[i] : 0.0f;
}

// ---------------------------------------------------------------------------
extern "C" void kernel_launch(void* const* d_in, const int* in_sizes, int n_in,
                              void* d_out, int out_size) {
    const float* thin = (const float*)d_in[0];
    float* out = (float*)d_out;

    k_lowhigh<<<NPIX / 256, 256>>>(thin, out);

    dim3 bpB(32, 8);
    dim3 bpG(IMG_W / 32, NWORDS / 8);
    k_bitpack<<<bpG, bpB>>>(thin);

    k_trace<<<1, 32>>>();

    k_final<<<NPIX / 256, 256>>>(thin, out);
}

// round 2
// speedup vs baseline: 2.5020x; 2.5020x over previous
#include <cuda_runtime.h>

typedef unsigned long long u64;
typedef unsigned int u32;

#define IMG_W 2048
#define IMG_H 2048
#define NWORDS 32               // 32 x u64 = 2048 bits per column
#define NPIX (IMG_W * IMG_H)

// Bit grids, column-major: word (c, w) holds rows [64w, 64w+63] of column c.
__device__ u64 d_A[IMG_W * NWORDS];   // active mask (starts as thin >= 3)
__device__ u64 d_L[IMG_W * NWORDS];   // weak mask   (thin >= 1)

// ---------------------------------------------------------------------------
// Fused: low/high outputs + bitpack of L and initial A.
// Thread (c, w) handles rows [64w, 64w+63] of column c. Warp spans 32
// consecutive columns -> every row-step is a coalesced 128B transaction.
// ---------------------------------------------------------------------------
__global__ void k_prep(const float* __restrict__ thin, float* __restrict__ out) {
    int c = blockIdx.x * 32 + threadIdx.x;
    int w = blockIdx.y * blockDim.y + threadIdx.y;
    u64 L = 0, A = 0;
    size_t base = (size_t)(w * 64) * IMG_W + c;
    #pragma unroll 8
    for (int b = 0; b < 64; ++b) {
        size_t idx = base + (size_t)b * IMG_W;
        float v = thin[idx];
        bool lo = (v >= 1.0f), hi = (v >= 3.0f);
        out[idx]        = lo ? v : 0.0f;   // low
        out[NPIX + idx] = hi ? v : 0.0f;   // high
        L |= ((u64)lo) << b;
        A |= ((u64)hi) << b;
    }
    d_L[c * NWORDS + w] = L;
    d_A[c * NWORDS + w] = A;
}

// ---------------------------------------------------------------------------
// One directional trace pass, single warp. Lane k owns 64 virtual rows
// (for YR passes virtual rows are the mirror of real rows: brevll + lane
// mirror at load/store; gmem grids stay in canonical orientation).
//
// Per column: gated-or scan s_i = g_i | (p_i & s_{i-1}) == carry chain of
// p+g (g subset p). Cross-lane carries via 2 ballots + one scalar 33-bit
// add. Speculative cb0/cb1 precomputed so only a SEL follows the ballot.
// ---------------------------------------------------------------------------
template <bool XR, bool YR>
__device__ __forceinline__ void trace_pass(const int lane) {
    const u32 FULL = 0xffffffffu;
    const int gw = YR ? (NWORDS - 1 - lane) : lane;

    u64 INTM = ~0ull;
    if (lane == 0)          INTM &= ~1ull;                   // virtual row 0
    if (lane == NWORDS - 1) INTM &= 0x7fffffffffffffffull;   // virtual row 2047

    const int dx = XR ? -1 : 1;
    const int cx0 = XR ? (IMG_W - 2) : 1;

    u64*       Abase = d_A + gw;
    const u64* Lbase = d_L + gw;

    auto ldA = [&](int c) -> u64 { u64 v = Abase[c * NWORDS]; return YR ? __brevll(v) : v; };
    auto ldL = [&](int c) -> u64 { u64 v = Lbase[c * NWORDS]; return YR ? __brevll(v) : v; };
    auto stA = [&](int c, u64 v) { Abase[c * NWORDS] = YR ? __brevll(v) : v; };

    // state + 6-deep prefetch ring (ring[j] consumed at step k where k%6==j)
    u64 Aprev = ldA(cx0 - dx), Acur = ldA(cx0), Anext = ldA(cx0 + dx);
    u64 Lprev = ldL(cx0 - dx), Lcur = ldL(cx0), Lnext = ldL(cx0 + dx);
    u64 Ab[6], Lb[6];
    #pragma unroll
    for (int j = 0; j < 6; ++j) {
        Ab[j] = ldA(cx0 + (2 + j) * dx);
        Lb[j] = ldL(cx0 + (2 + j) * dx);
    }

    int cx = cx0;
    for (int blk = 0; blk < (IMG_W - 2) / 6; ++blk) {        // 341 blocks x 6
        #pragma unroll
        for (int j = 0; j < 6; ++j) {
            u64 g = Acur & INTM;
            u64 p = Lcur & INTM;
            u64 sum0 = p + g;
            u64 sum1 = sum0 + 1;
            bool predG = sum0 < p;          // carry-out, cin=0
            bool predP = (sum0 == ~0ull);   // propagates cin
            bool g0 = ((u32)g & 1u) != 0u;
            bool p0 = ((u32)p & 1u) != 0u;
            u32 G   = __ballot_sync(FULL, predG);
            u32 P   = __ballot_sync(FULL, predP);
            u32 Bg0 = __ballot_sync(FULL, g0);
            u32 Bp0 = __ballot_sync(FULL, p0);
            u64 cb0 = sum0 ^ p ^ g;         // speculative (cin=0)
            u64 cb1 = sum1 ^ p ^ g;         // speculative (cin=1)
            u64 C = ((u64)P + (u64)G) ^ (u64)P ^ (u64)G;   // per-lane cin mask (+bit32)
            u64 Cs = C >> lane;             // bit0=cin, bit1=carry-out of this lane
            u64 cin = Cs & 1ull;
            u64 cb = cin ? cb1 : cb0;
            u64 s = (cb >> 1) | ((Cs & 2ull) << 62);
            u32 S0 = Bg0 | (Bp0 & (u32)C);  // bit0 of s per lane (scalar)
            u64 up = (s >> 1) | ((((u64)S0 >> lane) & 2ull) << 62);
            u64 dn = (s << 1) | cin;
            u64 mid  = up | dn;
            u64 side = mid | s;

            stA(cx - dx, Aprev | (side & Lprev));   // final for this pass
            Aprev = Acur  | (mid  & Lcur);
            Acur  = Anext | (side & Lnext);         // critical recurrence
            Anext = Ab[j];
            Lprev = Lcur; Lcur = Lnext; Lnext = Lb[j];

            int lc = cx + 8 * dx;                    // refill for step +6
            if ((u32)lc < (u32)IMG_W) { Ab[j] = ldA(lc); Lb[j] = ldL(lc); }
            cx += dx;
        }
    }
    // flush the last two columns
    stA(cx - dx, Aprev);
    stA(cx, Acur);
}

__global__ void __launch_bounds__(32, 1) k_trace() {
    const int lane = threadIdx.x;
    trace_pass<false, false>(lane);
    __threadfence_block(); __syncwarp();
    trace_pass<true, true>(lane);
    __threadfence_block(); __syncwarp();
    trace_pass<false, true>(lane);
    __threadfence_block(); __syncwarp();
    trace_pass<true, false>(lane);
}

// ---------------------------------------------------------------------------
// final = A ? thin : 0
// ---------------------------------------------------------------------------
__global__ void k_final(const float* __restrict__ thin, float* __restrict__ out) {
    int i = blockIdx.x * blockDim.x + threadIdx.x;
    int r = i >> 11;
    int c = i & (IMG_W - 1);
    u64 w = d_A[c * NWORDS + (r >> 6)];
    bool act = (w >> (r & 63)) & 1ull;
    out[2 * NPIX + i] = act ? thin[i] : 0.0f;
}

// ---------------------------------------------------------------------------
extern "C" void kernel_launch(void* const* d_in, const int* in_sizes, int n_in,
                              void* d_out, int out_size) {
    const float* thin = (const float*)d_in[0];
    float* out = (float*)d_out;

    dim3 bpB(32, 8);
    dim3 bpG(IMG_W / 32, NWORDS / 8);
    k_prep<<<bpG, bpB>>>(thin, out);

    k_trace<<<1, 32>>>();

    k_final<<<NPIX / 256, 256>>>(thin, out);
}

// round 3
// speedup vs baseline: 3.0038x; 1.2006x over previous
#include <cuda_runtime.h>

typedef unsigned long long u64;
typedef unsigned int u32;

#define IMG_W 2048
#define IMG_H 2048
#define NWORDS 32               // 32 x u64 = 2048 bits per column
#define NPIX (IMG_W * IMG_H)
#define COFF 8                  // column padding so prefetch never bounds-checks
#define NCOLS (IMG_W + 2 * COFF)

// Interleaved bit grids, column-major: elem (c, w) = {A, L} for rows [64w, 64w+63].
__device__ ulonglong2 d_AL[NCOLS * NWORDS];

// ---------------------------------------------------------------------------
// Fused: low/high outputs + bitpack of {A = thin>=3, L = thin>=1}.
// ---------------------------------------------------------------------------
__global__ void k_prep(const float* __restrict__ thin, float* __restrict__ out) {
    int c = blockIdx.x * 32 + threadIdx.x;
    int w = blockIdx.y * blockDim.y + threadIdx.y;
    u64 L = 0, A = 0;
    size_t base = (size_t)(w * 64) * IMG_W + c;
    #pragma unroll 8
    for (int b = 0; b < 64; ++b) {
        size_t idx = base + (size_t)b * IMG_W;
        float v = thin[idx];
        bool lo = (v >= 1.0f), hi = (v >= 3.0f);
        out[idx]        = lo ? v : 0.0f;   // low
        out[NPIX + idx] = hi ? v : 0.0f;   // high
        L |= ((u64)lo) << b;
        A |= ((u64)hi) << b;
    }
    d_AL[(c + COFF) * NWORDS + w] = make_ulonglong2(A, L);
}

// ---------------------------------------------------------------------------
// One directional trace pass, single warp. Lane k owns 64 virtual rows.
// Gated-or scan == carry chain of p+g (g subset p); cross-lane carries via
// 2 ballots + one scalar 33-bit add. All neighbor smears expressed in the
// carry-bit word cb (dn == cb; s == cb>>1 | co<<63).
// ---------------------------------------------------------------------------
template <bool XR, bool YR>
__device__ __forceinline__ void trace_pass(const int lane) {
    const u32 FULL = 0xffffffffu;
    const int gw = YR ? (NWORDS - 1 - lane) : lane;

    u64 INTM = ~0ull;
    if (lane == 0)  INTM &= ~1ull;                   // virtual row 0
    if (lane == 31) INTM &= 0x7fffffffffffffffull;   // virtual row 2047
    const u32 notTop = (lane == 31) ? 0u : ~0u;

    const int dx = XR ? -1 : 1;
    const int cx0 = XR ? (IMG_W - 2) : 1;

    ulonglong2* base = d_AL + gw;

    auto ld = [&](int c, u64& A, u64& L) {
        ulonglong2 v = base[(c + COFF) * NWORDS];
        A = YR ? __brevll(v.x) : v.x;
        L = YR ? __brevll(v.y) : v.y;
    };
    auto stA = [&](int c, u64 v) {
        ((u64*)&base[(c + COFF) * NWORDS])[0] = YR ? __brevll(v) : v;
    };

    u64 Aprev, Acur, Anext, Lprev, Lcur, Lnext;
    ld(cx0 - dx, Aprev, Lprev);
    ld(cx0,      Acur,  Lcur);
    ld(cx0 + dx, Anext, Lnext);
    u64 Ab[6], Lb[6];
    #pragma unroll
    for (int j = 0; j < 6; ++j) ld(cx0 + (2 + j) * dx, Ab[j], Lb[j]);

    int cx = cx0;
    for (int blk = 0; blk < (IMG_W - 2) / 6; ++blk) {        // 341 x 6 = 2046
        #pragma unroll
        for (int j = 0; j < 6; ++j) {
            u64 g = Acur & INTM;
            u64 p = Lcur & INTM;
            u64 pxg = p ^ g;                                  // off-chain
            u32 b0 = ((u32)g & 1u) | (((u32)p << 1) & 2u);    // {g0, p0}
            u32 b0n = __shfl_down_sync(FULL, b0, 1) & notTop; // lane+1's bits
            u64 sum0 = p + g;
            u32 G = __ballot_sync(FULL, sum0 < p);            // lane carry-gen
            u32 P = __ballot_sync(FULL, sum0 == ~0ull);       // lane carry-prop
            u64 C  = ((u64)P + (u64)G) ^ (u64)(P ^ G);        // cin per lane (+bit32)
            u64 Cs = C >> lane;                               // bit0=cin, bit1=cout
            u64 cin = Cs & 1ull;
            u64 cb  = (sum0 + cin) ^ pxg;                     // carry-in bits == dn
            u32 cn1 = ((u32)Cs >> 1) & 1u;                    // cin of lane+1
            u32 s0n = (b0n & 1u) | ((b0n >> 1) & cn1);        // s bit0 of lane+1
            u64 co2 = Cs & 2ull;                              // cout at bit1
            u64 mid  = cb | (cb >> 2) | (co2 << 61) | ((u64)s0n << 63);
            u64 side = mid | (cb >> 1) | (co2 << 62);

            stA(cx - dx, Aprev | (side & Lprev));             // final this pass
            Aprev = Acur  | (mid  & Lcur);
            Acur  = Anext | (side & Lnext);                   // critical recurrence
            Anext = Ab[j];
            Lprev = Lcur; Lcur = Lnext; Lnext = Lb[j];
            ld(cx + 8 * dx, Ab[j], Lb[j]);                    // padded: no bounds check
            cx += dx;
        }
    }
    stA(cx - dx, Aprev);
    stA(cx, Acur);
}

__global__ void __launch_bounds__(32, 1) k_trace() {
    const int lane = threadIdx.x;
    trace_pass<false, false>(lane);
    __threadfence_block(); __syncwarp();
    trace_pass<true, true>(lane);
    __threadfence_block(); __syncwarp();
    trace_pass<false, true>(lane);
    __threadfence_block(); __syncwarp();
    trace_pass<true, false>(lane);
}

// ---------------------------------------------------------------------------
// final = A ? thin : 0.  Tile 64 rows x 32 cols per block; each thread owns
// one column-word and writes 8 coalesced pixels.
// ---------------------------------------------------------------------------
__global__ void k_final(const float* __restrict__ thin, float* __restrict__ out) {
    int c0 = blockIdx.x * 32;
    int r0 = blockIdx.y * 64;
    int lane = threadIdx.x & 31;
    int sub  = threadIdx.x >> 5;      // 0..7
    u64 wrd = d_AL[(c0 + lane + COFF) * NWORDS + (r0 >> 6)].x;
    #pragma unroll
    for (int k = 0; k < 8; ++k) {
        int rr = sub * 8 + k;
        size_t idx = (size_t)(r0 + rr) * IMG_W + c0 + lane;
        bool act = (wrd >> rr) & 1ull;
        out[2 * NPIX + idx] = act ? thin[idx] : 0.0f;
    }
}

// ---------------------------------------------------------------------------
extern "C" void kernel_launch(void* const* d_in, const int* in_sizes, int n_in,
                              void* d_out, int out_size) {
    const float* thin = (const float*)d_in[0];
    float* out = (float*)d_out;

    dim3 bpB(32, 8);
    dim3 bpG(IMG_W / 32, NWORDS / 8);
    k_prep<<<bpG, bpB>>>(thin, out);

    k_trace<<<1, 32>>>();

    dim3 fG(IMG_W / 32, IMG_H / 64);
    k_final<<<fG, 256>>>(thin, out);
}